// round 14
// baseline (speedup 1.0000x reference)
#include <cuda_runtime.h>
#include <cstdint>

// ---------------- device scratch ----------------
__device__ __align__(16) float g_act0[32 * 21504];
__device__ __align__(16) float g_act3[32 * 4096];
__device__ __align__(16) float g_act4[32 * 64];
__device__ __align__(16) float g_part[1048576];        // max(2*32*16384, 8*32*4096)
__device__ __align__(16) uint4 g_xpk0[172032];         // 21504/16 * 128
__device__ __align__(16) uint4 g_xpk1[131072];         // 16384/16 * 128
__device__ __align__(16) uint4 g_xpk2[32768];          // 4096/16 * 128

// ---------------- PTX helpers ----------------
__device__ __forceinline__ void mma16816(float* d, unsigned a0, unsigned a1, unsigned a2, unsigned a3,
                                         unsigned b0, unsigned b1) {
    asm volatile("mma.sync.aligned.m16n8k16.row.col.f32.bf16.bf16.f32 "
                 "{%0,%1,%2,%3}, {%4,%5,%6,%7}, {%8,%9}, {%0,%1,%2,%3};"
                 : "+f"(d[0]), "+f"(d[1]), "+f"(d[2]), "+f"(d[3])
                 : "r"(a0), "r"(a1), "r"(a2), "r"(a3), "r"(b0), "r"(b1));
}
__device__ __forceinline__ void cvt_hilo(float4 v, unsigned &h01, unsigned &h23,
                                         unsigned &l01, unsigned &l23) {
    asm("cvt.rn.bf16x2.f32 %0, %1, %2;" : "=r"(h01) : "f"(v.y), "f"(v.x));
    asm("cvt.rn.bf16x2.f32 %0, %1, %2;" : "=r"(h23) : "f"(v.w), "f"(v.z));
    float r0 = v.x - __uint_as_float(h01 << 16);
    float r1 = v.y - __uint_as_float(h01 & 0xffff0000u);
    float r2 = v.z - __uint_as_float(h23 << 16);
    float r3 = v.w - __uint_as_float(h23 & 0xffff0000u);
    asm("cvt.rn.bf16x2.f32 %0, %1, %2;" : "=r"(l01) : "f"(r1), "f"(r0));
    asm("cvt.rn.bf16x2.f32 %0, %1, %2;" : "=r"(l23) : "f"(r3), "f"(r2));
}
__device__ __forceinline__ void cp16(unsigned dst, const void* src) {
    asm volatile("cp.async.cg.shared.global [%0], [%1], 16;" :: "r"(dst), "l"(src));
}

// smem per stage: W fp32 128 rows x 320B (40960) + X packed 8192 = 49152; 2 stages
#define WROWB  320
#define STG    49152
#define XOFF   40960
#define SMEM_TOTAL (2 * STG)   // 98304 -> 2 CTAs/SM

// ---------------- conv + permuted scatter ----------------
__global__ void conv_kernel(const float* __restrict__ in,
                            const float* __restrict__ cw,
                            const float* __restrict__ cb) {
    int b = blockIdx.x >> 2, f = blockIdx.x & 3, tid = threadIdx.x;
    __shared__ float xin[343], wsh[128], bsh[16];
    for (int i = tid; i < 343; i += 128) xin[i] = in[(b * 343 + i) * 5 + f];
    if (tid < 128) wsh[tid] = cw[tid];
    if (tid < 16)  bsh[tid] = cb[tid];
    __syncthreads();
    int h = b >> 4, base = (b & 15) * 1344 + f * 336;
    for (int l = tid; l < 336; l += 128) {
        #pragma unroll
        for (int c = 0; c < 16; ++c) {
            float s = bsh[c];
            #pragma unroll
            for (int k = 0; k < 8; ++k) s += xin[l + k] * wsh[c * 8 + k];
            g_act0[(2 * c + h) * 21504 + base + l] = fmaxf(s, 0.f);
        }
    }
}

// ---------------- pack fp32 X[32][K] -> fragment-ordered bf16 hi/lo uint4 ----------------
__global__ void pack_kernel(const float* __restrict__ src, int K, uint4* __restrict__ dst) {
    int i = blockIdx.x * 256 + threadIdx.x;
    if (i >= (K >> 4) * 128) return;
    int kb = i >> 7, ng = (i >> 5) & 3, lane = i & 31;
    int b = ng * 8 + (lane >> 2), c = kb * 16 + (lane & 3) * 4;
    float4 v = *(const float4*)(src + (long)b * K + c);
    uint4 o;
    cvt_hilo(v, o.x, o.y, o.z, o.w);
    dst[i] = o;
}

// dummy so dense1 gemm lands at ncu's capture index
__global__ void marker_kernel() {}

// ---------------- split-K reduce + bias + relu -> packed X ----------------
__global__ void reduce_pack(const float* __restrict__ bias, int N, int ks, uint4* __restrict__ dst) {
    int i = blockIdx.x * 256 + threadIdx.x;
    if (i >= (N >> 4) * 128) return;
    int kb = i >> 7, ng = (i >> 5) & 3, lane = i & 31;
    int b = ng * 8 + (lane >> 2), c = kb * 16 + (lane & 3) * 4;
    float4 s = *(const float4*)(bias + c);
    for (int si = 0; si < ks; ++si) {
        float4 p = *(const float4*)(g_part + ((long)(si * 32 + b)) * N + c);
        s.x += p.x; s.y += p.y; s.z += p.z; s.w += p.w;
    }
    s.x = fmaxf(s.x, 0.f); s.y = fmaxf(s.y, 0.f);
    s.z = fmaxf(s.z, 0.f); s.w = fmaxf(s.w, 0.f);
    uint4 o;
    cvt_hilo(s, o.x, o.y, o.z, o.w);
    dst[i] = o;
}

// ---------------- split-K reduce + bias + relu -> fp32 (dense4 input) ----------------
__global__ void reduce_kernel(const float* __restrict__ bias, int N, int ks) {
    int idx = blockIdx.x * 256 + threadIdx.x;
    if (idx >= 32 * N) return;
    float s = bias[idx % N];
    for (int si = 0; si < ks; ++si) s += g_part[(long)si * 32 * N + idx];
    g_act3[idx] = fmaxf(s, 0.f);
}

// ---------------- bf16x3 mma.sync GEMM: cp.async staged, M=128 x N=32, slab 64 ----------------
__global__ __launch_bounds__(256, 2)
void gemm_mma(const float* __restrict__ W, const uint4* __restrict__ xpk,
              int N, int K, int nslabs) {
    extern __shared__ __align__(16) char smem[];
    unsigned sb = (unsigned)__cvta_generic_to_shared(smem);
    int tid = threadIdx.x, wid = tid >> 5, lane = tid & 31;
    int tile = blockIdx.x, ky = blockIdx.y;
    int r = lane >> 2, t = lane & 3;
    long k0 = (long)ky * nslabs * 64;

    // staging source pointers
    int srow = tid >> 1, shalf = tid & 1;                 // 2 threads per W row
    const float* wsrc = W + (long)(tile * 128 + srow) * K + k0 + shalf * 32;
    const uint4* xsrc = xpk + (long)(ky * nslabs * 4) * 128 + tid;

    auto load_slab = [&](int s) {
        unsigned bb = sb + (s & 1) * STG;
        unsigned wd = bb + srow * WROWB + shalf * 128;
        const float* wp = wsrc + (long)s * 64;
        #pragma unroll
        for (int i = 0; i < 8; ++i) cp16(wd + i * 16, wp + i * 4);
        unsigned xd = bb + XOFF + tid * 16;
        const uint4* xp = xsrc + (long)s * 512;
        cp16(xd, xp);
        cp16(xd + 4096, xp + 256);
        asm volatile("cp.async.commit_group;");
    };

    float acc[4][4];
    #pragma unroll
    for (int j = 0; j < 4; ++j)
        #pragma unroll
        for (int q = 0; q < 4; ++q) acc[j][q] = 0.f;

    load_slab(0);
    if (nslabs > 1) load_slab(1);

    for (int s = 0; s < nslabs; ++s) {
        if (s + 1 < nslabs) asm volatile("cp.async.wait_group 1;");
        else                asm volatile("cp.async.wait_group 0;");
        __syncthreads();

        unsigned bb = sb + (s & 1) * STG;
        const char* wbp = smem + (s & 1) * STG;
        const char* xbp = wbp + XOFF;
        #pragma unroll
        for (int ks = 0; ks < 4; ++ks) {
            float4 w0 = *(const float4*)(wbp + (wid * 16 + r) * WROWB + ks * 64 + t * 16);
            float4 w1 = *(const float4*)(wbp + (wid * 16 + r + 8) * WROWB + ks * 64 + t * 16);
            unsigned a0h, a2h, a0l, a2l, a1h, a3h, a1l, a3l;
            cvt_hilo(w0, a0h, a2h, a0l, a2l);
            cvt_hilo(w1, a1h, a3h, a1l, a3l);
            #pragma unroll
            for (int ng = 0; ng < 4; ++ng) {
                uint4 u = *(const uint4*)(xbp + ks * 2048 + ng * 512 + lane * 16);
                mma16816(acc[ng], a0h, a1h, a2h, a3h, u.x, u.y);
                mma16816(acc[ng], a0h, a1h, a2h, a3h, u.z, u.w);
                mma16816(acc[ng], a0l, a1l, a2l, a3l, u.x, u.y);
            }
        }
        __syncthreads();
        if (s + 2 < nslabs) load_slab(s + 2);
        (void)bb;
    }

    // epilogue: raw split-K partials (mapping validated R10/R11)
    int n0 = tile * 128 + wid * 16 + r;
    #pragma unroll
    for (int nf = 0; nf < 4; ++nf) {
        int b0 = nf * 8 + 2 * t;
        g_part[(long)(ky * 32 + b0)     * N + n0]     = acc[nf][0];
        g_part[(long)(ky * 32 + b0 + 1) * N + n0]     = acc[nf][1];
        g_part[(long)(ky * 32 + b0)     * N + n0 + 8] = acc[nf][2];
        g_part[(long)(ky * 32 + b0 + 1) * N + n0 + 8] = acc[nf][3];
    }
}

// ---------------- dense4 (4096 -> 64) ----------------
__global__ void dense4_kernel(const float* __restrict__ w4, const float* __restrict__ b4) {
    int n = blockIdx.x, tid = threadIdx.x;
    float acc[32];
    #pragma unroll
    for (int b = 0; b < 32; ++b) acc[b] = 0.f;
    const float* wr = w4 + n * 4096;
    for (int k = tid; k < 4096; k += 128) {
        float w = wr[k];
        #pragma unroll
        for (int b = 0; b < 32; ++b) acc[b] += g_act3[b * 4096 + k] * w;
    }
    __shared__ float red[4][32];
    int lane = tid & 31, wrp = tid >> 5;
    #pragma unroll
    for (int b = 0; b < 32; ++b) {
        float v = acc[b];
        v += __shfl_down_sync(0xffffffffu, v, 16);
        v += __shfl_down_sync(0xffffffffu, v, 8);
        v += __shfl_down_sync(0xffffffffu, v, 4);
        v += __shfl_down_sync(0xffffffffu, v, 2);
        v += __shfl_down_sync(0xffffffffu, v, 1);
        if (lane == 0) red[wrp][b] = v;
    }
    __syncthreads();
    if (tid < 32) {
        float s = red[0][tid] + red[1][tid] + red[2][tid] + red[3][tid] + b4[n];
        g_act4[tid * 64 + n] = fmaxf(s, 0.f);
    }
}

// ---------------- fused output (64 -> 16 -> 1) ----------------
__global__ void final_kernel(const float* __restrict__ wo, const float* __restrict__ bo,
                             const float* __restrict__ wf, const float* __restrict__ bf,
                             float* __restrict__ out) {
    int b = threadIdx.x;
    float res = bf[0];
    for (int j = 0; j < 16; ++j) {
        float o = bo[j];
        #pragma unroll
        for (int n = 0; n < 64; ++n) o += g_act4[b * 64 + n] * wo[j * 64 + n];
        res += o * wf[j];
    }
    out[b] = res;
}

extern "C" void kernel_launch(void* const* d_in, const int* in_sizes, int n_in,
                              void* d_out, int out_size) {
    const float* in  = (const float*)d_in[0];
    const float* cw  = (const float*)d_in[4];
    const float* cb  = (const float*)d_in[5];
    const float* w1  = (const float*)d_in[6];
    const float* b1  = (const float*)d_in[7];
    const float* w2  = (const float*)d_in[8];
    const float* b2  = (const float*)d_in[9];
    const float* w3  = (const float*)d_in[10];
    const float* b3  = (const float*)d_in[11];
    const float* w4  = (const float*)d_in[12];
    const float* b4  = (const float*)d_in[13];
    const float* wo  = (const float*)d_in[14];
    const float* bo  = (const float*)d_in[15];
    const float* wf  = (const float*)d_in[16];
    const float* bf  = (const float*)d_in[17];
    float* out = (float*)d_out;

    float *act0;
    uint4 *xpk0, *xpk1, *xpk2;
    cudaGetSymbolAddress((void**)&act0, g_act0);
    cudaGetSymbolAddress((void**)&xpk0, g_xpk0);
    cudaGetSymbolAddress((void**)&xpk1, g_xpk1);
    cudaGetSymbolAddress((void**)&xpk2, g_xpk2);

    cudaFuncSetAttribute(gemm_mma, cudaFuncAttributeMaxDynamicSharedMemorySize, SMEM_TOTAL);

    conv_kernel<<<128, 128>>>(in, cw, cb);
    pack_kernel<<<672, 256>>>(act0, 21504, xpk0);
    marker_kernel<<<1, 32>>>();   // aligns dense1 gemm to ncu capture slot

    // dense1: 16384x21504 -> 128 tiles x split 2 = 256 CTAs, 168 slabs
    gemm_mma<<<dim3(128, 2), 256, SMEM_TOTAL>>>(w1, xpk0, 16384, 21504, 168);
    reduce_pack<<<512, 256>>>(b1, 16384, 2, xpk1);

    // dense2: 4096x16384 -> 32 tiles x split 8 = 256 CTAs, 32 slabs
    gemm_mma<<<dim3(32, 8), 256, SMEM_TOTAL>>>(w2, xpk1, 4096, 16384, 32);
    reduce_pack<<<128, 256>>>(b2, 4096, 8, xpk2);

    // dense3: 4096x4096 -> 32 tiles x split 8 = 256 CTAs, 8 slabs (fp32 out for dense4)
    gemm_mma<<<dim3(32, 8), 256, SMEM_TOTAL>>>(w3, xpk2, 4096, 4096, 8);
    reduce_kernel<<<512, 256>>>(b3, 4096, 8);

    dense4_kernel<<<64, 128>>>(w4, b4);
    final_kernel<<<1, 32>>>(wo, bo, wf, bf, out);
}

// round 15
// speedup vs baseline: 1.1261x; 1.1261x over previous
#include <cuda_runtime.h>
#include <cstdint>

// ---------------- device scratch ----------------
__device__ __align__(16) float g_act0[32 * 21504];
__device__ __align__(16) float g_act3[32 * 4096];
__device__ __align__(16) float g_act4[32 * 64];
__device__ __align__(16) float g_part[2097152];        // 4*32*16384 == 16*32*4096
__device__ __align__(16) uint4 g_xpk0[172032];         // 21504/16 * 128
__device__ __align__(16) uint4 g_xpk1[131072];         // 16384/16 * 128
__device__ __align__(16) uint4 g_xpk2[32768];          // 4096/16 * 128

// ---------------- PTX helpers ----------------
__device__ __forceinline__ void mma16816(float* d, unsigned a0, unsigned a1, unsigned a2, unsigned a3,
                                         unsigned b0, unsigned b1) {
    asm volatile("mma.sync.aligned.m16n8k16.row.col.f32.bf16.bf16.f32 "
                 "{%0,%1,%2,%3}, {%4,%5,%6,%7}, {%8,%9}, {%0,%1,%2,%3};"
                 : "+f"(d[0]), "+f"(d[1]), "+f"(d[2]), "+f"(d[3])
                 : "r"(a0), "r"(a1), "r"(a2), "r"(a3), "r"(b0), "r"(b1));
}
// float4 -> {hi01, hi23, lo01, lo23} packed bf16x2
__device__ __forceinline__ void cvt_hilo(float4 v, unsigned &h01, unsigned &h23,
                                         unsigned &l01, unsigned &l23) {
    asm("cvt.rn.bf16x2.f32 %0, %1, %2;" : "=r"(h01) : "f"(v.y), "f"(v.x));
    asm("cvt.rn.bf16x2.f32 %0, %1, %2;" : "=r"(h23) : "f"(v.w), "f"(v.z));
    float r0 = v.x - __uint_as_float(h01 << 16);
    float r1 = v.y - __uint_as_float(h01 & 0xffff0000u);
    float r2 = v.z - __uint_as_float(h23 << 16);
    float r3 = v.w - __uint_as_float(h23 & 0xffff0000u);
    asm("cvt.rn.bf16x2.f32 %0, %1, %2;" : "=r"(l01) : "f"(r1), "f"(r0));
    asm("cvt.rn.bf16x2.f32 %0, %1, %2;" : "=r"(l23) : "f"(r3), "f"(r2));
}

// ---------------- conv + permuted scatter ----------------
__global__ void conv_kernel(const float* __restrict__ in,
                            const float* __restrict__ cw,
                            const float* __restrict__ cb) {
    int b = blockIdx.x >> 2, f = blockIdx.x & 3, tid = threadIdx.x;
    __shared__ float xin[343], wsh[128], bsh[16];
    for (int i = tid; i < 343; i += 128) xin[i] = in[(b * 343 + i) * 5 + f];
    if (tid < 128) wsh[tid] = cw[tid];
    if (tid < 16)  bsh[tid] = cb[tid];
    __syncthreads();
    int h = b >> 4, base = (b & 15) * 1344 + f * 336;
    for (int l = tid; l < 336; l += 128) {
        #pragma unroll
        for (int c = 0; c < 16; ++c) {
            float s = bsh[c];
            #pragma unroll
            for (int k = 0; k < 8; ++k) s += xin[l + k] * wsh[c * 8 + k];
            g_act0[(2 * c + h) * 21504 + base + l] = fmaxf(s, 0.f);
        }
    }
}

// ---------------- pack fp32 X[32][K] -> fragment-ordered bf16 hi/lo uint4 ----------------
__global__ void pack_kernel(const float* __restrict__ src, int K, uint4* __restrict__ dst) {
    int i = blockIdx.x * 256 + threadIdx.x;
    if (i >= (K >> 4) * 128) return;
    int kb = i >> 7, ng = (i >> 5) & 3, lane = i & 31;
    int b = ng * 8 + (lane >> 2), c = kb * 16 + (lane & 3) * 4;
    float4 v = *(const float4*)(src + (long)b * K + c);
    uint4 o;
    cvt_hilo(v, o.x, o.y, o.z, o.w);
    dst[i] = o;
}

// dummy so dense1 gemm lands at ncu's capture index
__global__ void marker_kernel() {}

// ---------------- split-K reduce + bias + relu -> packed X ----------------
__global__ void reduce_pack(const float* __restrict__ bias, int N, int ks, uint4* __restrict__ dst) {
    int i = blockIdx.x * 256 + threadIdx.x;
    if (i >= (N >> 4) * 128) return;
    int kb = i >> 7, ng = (i >> 5) & 3, lane = i & 31;
    int b = ng * 8 + (lane >> 2), c = kb * 16 + (lane & 3) * 4;
    float4 s = *(const float4*)(bias + c);
    for (int si = 0; si < ks; ++si) {
        float4 p = *(const float4*)(g_part + ((long)(si * 32 + b)) * N + c);
        s.x += p.x; s.y += p.y; s.z += p.z; s.w += p.w;
    }
    s.x = fmaxf(s.x, 0.f); s.y = fmaxf(s.y, 0.f);
    s.z = fmaxf(s.z, 0.f); s.w = fmaxf(s.w, 0.f);
    uint4 o;
    cvt_hilo(s, o.x, o.y, o.z, o.w);
    dst[i] = o;
}

// ---------------- split-K reduce + bias + relu -> fp32 (dense4 input) ----------------
__global__ void reduce_kernel(const float* __restrict__ bias, int N, int ks) {
    int idx = blockIdx.x * 256 + threadIdx.x;
    if (idx >= 32 * N) return;
    float s = bias[idx % N];
    for (int si = 0; si < ks; ++si) s += g_part[(long)si * 32 * N + idx];
    g_act3[idx] = fmaxf(s, 0.f);
}

// ---------------- bf16x3 mma.sync GEMM: LDG-direct (R11 mapping), occ-3, staggered ----------------
// D[n,b] = sum_k W[n,k]*X[b,k]; tile M=128 x N=32, slab k=64, split-K raw partials.
__global__ __launch_bounds__(256, 3)
void gemm_mma(const float* __restrict__ W, const uint4* __restrict__ xpk,
              int N, int K, int nslabs) {
    int tid = threadIdx.x, wid = tid >> 5, lane = tid & 31;
    int tile = blockIdx.x, ky = blockIdx.y;
    int r = lane >> 2, t = lane & 3;
    long k0 = (long)ky * nslabs * 64;

    const float* wp0 = W + (long)(tile * 128 + wid * 16 + r) * K + k0 + t * 4;
    const float* wp1 = wp0 + 8L * K;
    const uint4* xbase = xpk + (long)(ky * nslabs * 4) * 128 + lane;

    // stagger slab order across CTAs to decorrelate power-of-2 W strides
    int start = (tile * 7 + ky * 3) % nslabs;

    float acc[4][4];
    #pragma unroll
    for (int i = 0; i < 4; ++i)
        #pragma unroll
        for (int j = 0; j < 4; ++j) acc[i][j] = 0.f;

    for (int si = 0; si < nslabs; ++si) {
        int s = si + start;
        if (s >= nslabs) s -= nslabs;
        long sk = (long)s * 64;
        #pragma unroll
        for (int ks = 0; ks < 4; ++ks) {
            float4 w0 = __ldg((const float4*)(wp0 + sk + ks * 16));
            float4 w1 = __ldg((const float4*)(wp1 + sk + ks * 16));
            unsigned a0h, a2h, a0l, a2l, a1h, a3h, a1l, a3l;
            cvt_hilo(w0, a0h, a2h, a0l, a2l);     // row r:   a0=(k01) a2=(k23)
            cvt_hilo(w1, a1h, a3h, a1l, a3l);     // row r+8
            const uint4* xq = xbase + (long)(s * 4 + ks) * 128;
            #pragma unroll
            for (int ng = 0; ng < 4; ++ng) {
                uint4 u = __ldg(xq + ng * 32);    // {bh0, bh1, bl0, bl1}
                mma16816(acc[ng], a0h, a1h, a2h, a3h, u.x, u.y);
                mma16816(acc[ng], a0h, a1h, a2h, a3h, u.z, u.w);
                mma16816(acc[ng], a0l, a1l, a2l, a3l, u.x, u.y);
            }
        }
    }

    // epilogue: raw split-K partials (mapping validated R10/R11)
    int n0 = tile * 128 + wid * 16 + r;
    #pragma unroll
    for (int nf = 0; nf < 4; ++nf) {
        int b0 = nf * 8 + 2 * t;
        g_part[(long)(ky * 32 + b0)     * N + n0]     = acc[nf][0];
        g_part[(long)(ky * 32 + b0 + 1) * N + n0]     = acc[nf][1];
        g_part[(long)(ky * 32 + b0)     * N + n0 + 8] = acc[nf][2];
        g_part[(long)(ky * 32 + b0 + 1) * N + n0 + 8] = acc[nf][3];
    }
}

// ---------------- dense4 (4096 -> 64) ----------------
__global__ void dense4_kernel(const float* __restrict__ w4, const float* __restrict__ b4) {
    int n = blockIdx.x, tid = threadIdx.x;
    float acc[32];
    #pragma unroll
    for (int b = 0; b < 32; ++b) acc[b] = 0.f;
    const float* wr = w4 + n * 4096;
    for (int k = tid; k < 4096; k += 128) {
        float w = wr[k];
        #pragma unroll
        for (int b = 0; b < 32; ++b) acc[b] += g_act3[b * 4096 + k] * w;
    }
    __shared__ float red[4][32];
    int lane = tid & 31, wrp = tid >> 5;
    #pragma unroll
    for (int b = 0; b < 32; ++b) {
        float v = acc[b];
        v += __shfl_down_sync(0xffffffffu, v, 16);
        v += __shfl_down_sync(0xffffffffu, v, 8);
        v += __shfl_down_sync(0xffffffffu, v, 4);
        v += __shfl_down_sync(0xffffffffu, v, 2);
        v += __shfl_down_sync(0xffffffffu, v, 1);
        if (lane == 0) red[wrp][b] = v;
    }
    __syncthreads();
    if (tid < 32) {
        float s = red[0][tid] + red[1][tid] + red[2][tid] + red[3][tid] + b4[n];
        g_act4[tid * 64 + n] = fmaxf(s, 0.f);
    }
}

// ---------------- fused output (64 -> 16 -> 1) ----------------
__global__ void final_kernel(const float* __restrict__ wo, const float* __restrict__ bo,
                             const float* __restrict__ wf, const float* __restrict__ bf,
                             float* __restrict__ out) {
    int b = threadIdx.x;
    float res = bf[0];
    for (int j = 0; j < 16; ++j) {
        float o = bo[j];
        #pragma unroll
        for (int n = 0; n < 64; ++n) o += g_act4[b * 64 + n] * wo[j * 64 + n];
        res += o * wf[j];
    }
    out[b] = res;
}

extern "C" void kernel_launch(void* const* d_in, const int* in_sizes, int n_in,
                              void* d_out, int out_size) {
    const float* in  = (const float*)d_in[0];
    const float* cw  = (const float*)d_in[4];
    const float* cb  = (const float*)d_in[5];
    const float* w1  = (const float*)d_in[6];
    const float* b1  = (const float*)d_in[7];
    const float* w2  = (const float*)d_in[8];
    const float* b2  = (const float*)d_in[9];
    const float* w3  = (const float*)d_in[10];
    const float* b3  = (const float*)d_in[11];
    const float* w4  = (const float*)d_in[12];
    const float* b4  = (const float*)d_in[13];
    const float* wo  = (const float*)d_in[14];
    const float* bo  = (const float*)d_in[15];
    const float* wf  = (const float*)d_in[16];
    const float* bf  = (const float*)d_in[17];
    float* out = (float*)d_out;

    float *act0;
    uint4 *xpk0, *xpk1, *xpk2;
    cudaGetSymbolAddress((void**)&act0, g_act0);
    cudaGetSymbolAddress((void**)&xpk0, g_xpk0);
    cudaGetSymbolAddress((void**)&xpk1, g_xpk1);
    cudaGetSymbolAddress((void**)&xpk2, g_xpk2);

    conv_kernel<<<128, 128>>>(in, cw, cb);
    pack_kernel<<<672, 256>>>(act0, 21504, xpk0);
    marker_kernel<<<1, 32>>>();   // aligns dense1 gemm to ncu capture slot

    // dense1: 16384x21504 -> 128 tiles x split 4 = 512 CTAs, 84 slabs
    gemm_mma<<<dim3(128, 4), 256>>>(w1, xpk0, 16384, 21504, 84);
    reduce_pack<<<512, 256>>>(b1, 16384, 4, xpk1);

    // dense2: 4096x16384 -> 32 tiles x split 16 = 512 CTAs, 16 slabs
    gemm_mma<<<dim3(32, 16), 256>>>(w2, xpk1, 4096, 16384, 16);
    reduce_pack<<<128, 256>>>(b2, 4096, 16, xpk2);

    // dense3: 4096x4096 -> 32 tiles x split 16 = 512 CTAs, 4 slabs (fp32 out for dense4)
    gemm_mma<<<dim3(32, 16), 256>>>(w3, xpk2, 4096, 4096, 4);
    reduce_kernel<<<512, 256>>>(b3, 4096, 16);

    dense4_kernel<<<64, 128>>>(w4, b4);
    final_kernel<<<1, 32>>>(wo, bo, wf, bf, out);
}

// round 16
// speedup vs baseline: 1.2373x; 1.0988x over previous
#include <cuda_runtime.h>
#include <cstdint>

// ---------------- device scratch ----------------
__device__ __align__(16) float g_act0[32 * 21504];
__device__ __align__(16) float g_act3[32 * 4096];
__device__ __align__(16) float g_act4[32 * 64];
__device__ __align__(16) float g_part[1048576];        // max(2*32*16384, 8*32*4096)
__device__ __align__(16) uint4 g_xpk0[172032];         // 21504/16 * 128
__device__ __align__(16) uint4 g_xpk1[131072];         // 16384/16 * 128
__device__ __align__(16) uint4 g_xpk2[32768];          // 4096/16 * 128

// ---------------- PTX helpers ----------------
__device__ __forceinline__ void mma16816(float* d, unsigned a0, unsigned a1, unsigned a2, unsigned a3,
                                         unsigned b0, unsigned b1) {
    asm volatile("mma.sync.aligned.m16n8k16.row.col.f32.bf16.bf16.f32 "
                 "{%0,%1,%2,%3}, {%4,%5,%6,%7}, {%8,%9}, {%0,%1,%2,%3};"
                 : "+f"(d[0]), "+f"(d[1]), "+f"(d[2]), "+f"(d[3])
                 : "r"(a0), "r"(a1), "r"(a2), "r"(a3), "r"(b0), "r"(b1));
}
// float4 -> {hi01, hi23, lo01, lo23} packed bf16x2
__device__ __forceinline__ void cvt_hilo(float4 v, unsigned &h01, unsigned &h23,
                                         unsigned &l01, unsigned &l23) {
    asm("cvt.rn.bf16x2.f32 %0, %1, %2;" : "=r"(h01) : "f"(v.y), "f"(v.x));
    asm("cvt.rn.bf16x2.f32 %0, %1, %2;" : "=r"(h23) : "f"(v.w), "f"(v.z));
    float r0 = v.x - __uint_as_float(h01 << 16);
    float r1 = v.y - __uint_as_float(h01 & 0xffff0000u);
    float r2 = v.z - __uint_as_float(h23 << 16);
    float r3 = v.w - __uint_as_float(h23 & 0xffff0000u);
    asm("cvt.rn.bf16x2.f32 %0, %1, %2;" : "=r"(l01) : "f"(r1), "f"(r0));
    asm("cvt.rn.bf16x2.f32 %0, %1, %2;" : "=r"(l23) : "f"(r3), "f"(r2));
}

// ---------------- conv + permuted scatter ----------------
__global__ void conv_kernel(const float* __restrict__ in,
                            const float* __restrict__ cw,
                            const float* __restrict__ cb) {
    int b = blockIdx.x >> 2, f = blockIdx.x & 3, tid = threadIdx.x;
    __shared__ float xin[343], wsh[128], bsh[16];
    for (int i = tid; i < 343; i += 128) xin[i] = in[(b * 343 + i) * 5 + f];
    if (tid < 128) wsh[tid] = cw[tid];
    if (tid < 16)  bsh[tid] = cb[tid];
    __syncthreads();
    int h = b >> 4, base = (b & 15) * 1344 + f * 336;
    for (int l = tid; l < 336; l += 128) {
        #pragma unroll
        for (int c = 0; c < 16; ++c) {
            float s = bsh[c];
            #pragma unroll
            for (int k = 0; k < 8; ++k) s += xin[l + k] * wsh[c * 8 + k];
            g_act0[(2 * c + h) * 21504 + base + l] = fmaxf(s, 0.f);
        }
    }
}

// ---------------- pack fp32 X[32][K] -> fragment-ordered bf16 hi/lo uint4 ----------------
__global__ void pack_kernel(const float* __restrict__ src, int K, uint4* __restrict__ dst) {
    int i = blockIdx.x * 256 + threadIdx.x;
    if (i >= (K >> 4) * 128) return;
    int kb = i >> 7, ng = (i >> 5) & 3, lane = i & 31;
    int b = ng * 8 + (lane >> 2), c = kb * 16 + (lane & 3) * 4;
    float4 v = *(const float4*)(src + (long)b * K + c);
    uint4 o;
    cvt_hilo(v, o.x, o.y, o.z, o.w);
    dst[i] = o;
}

// dummy so dense1 gemm lands at ncu's capture index
__global__ void marker_kernel() {}

// ---------------- split-K reduce + bias + relu -> packed X ----------------
__global__ void reduce_pack(const float* __restrict__ bias, int N, int ks, uint4* __restrict__ dst) {
    int i = blockIdx.x * 256 + threadIdx.x;
    if (i >= (N >> 4) * 128) return;
    int kb = i >> 7, ng = (i >> 5) & 3, lane = i & 31;
    int b = ng * 8 + (lane >> 2), c = kb * 16 + (lane & 3) * 4;
    float4 s = *(const float4*)(bias + c);
    for (int si = 0; si < ks; ++si) {
        float4 p = *(const float4*)(g_part + ((long)(si * 32 + b)) * N + c);
        s.x += p.x; s.y += p.y; s.z += p.z; s.w += p.w;
    }
    s.x = fmaxf(s.x, 0.f); s.y = fmaxf(s.y, 0.f);
    s.z = fmaxf(s.z, 0.f); s.w = fmaxf(s.w, 0.f);
    uint4 o;
    cvt_hilo(s, o.x, o.y, o.z, o.w);
    dst[i] = o;
}

// ---------------- split-K reduce + bias + relu -> fp32 (dense4 input) ----------------
__global__ void reduce_kernel(const float* __restrict__ bias, int N, int ks) {
    int idx = blockIdx.x * 256 + threadIdx.x;
    if (idx >= 32 * N) return;
    float s = bias[idx % N];
    for (int si = 0; si < ks; ++si) s += g_part[(long)si * 32 * N + idx];
    g_act3[idx] = fmaxf(s, 0.f);
}

// ---------------- bf16x3 mma.sync GEMM: LDG-direct, explicit 1-step register pipeline ----------------
// D[n,b] = sum_k W[n,k]*X[b,k]; tile M=128 x N=32; step = k16; split-K raw partials.
__global__ __launch_bounds__(256, 2)
void gemm_mma(const float* __restrict__ W, const uint4* __restrict__ xpk,
              int N, int K, int nsteps) {
    int tid = threadIdx.x, wid = tid >> 5, lane = tid & 31;
    int tile = blockIdx.x, ky = blockIdx.y;
    int r = lane >> 2, t = lane & 3;
    long k0 = (long)ky * nsteps * 16;

    const float* wp0 = W + (long)(tile * 128 + wid * 16 + r) * K + k0 + t * 4;
    const float* wp1 = wp0 + 8L * K;
    const uint4* xbase = xpk + (long)(ky * nsteps) * 128 + lane;

    float acc[4][4];
    #pragma unroll
    for (int i = 0; i < 4; ++i)
        #pragma unroll
        for (int j = 0; j < 4; ++j) acc[i][j] = 0.f;

    // pipeline registers
    float4 w0c, w1c;
    uint4 xc0, xc1, xc2, xc3;

    // prologue: load step 0
    w0c = __ldg((const float4*)(wp0));
    w1c = __ldg((const float4*)(wp1));
    {
        const uint4* xq = xbase;
        xc0 = __ldg(xq);
        xc1 = __ldg(xq + 32);
        xc2 = __ldg(xq + 64);
        xc3 = __ldg(xq + 96);
    }

    for (int g = 0; g < nsteps; ++g) {
        // prefetch step g+1
        float4 w0n, w1n;
        uint4 xn0, xn1, xn2, xn3;
        if (g + 1 < nsteps) {
            long o = (long)(g + 1) * 16;
            w0n = __ldg((const float4*)(wp0 + o));
            w1n = __ldg((const float4*)(wp1 + o));
            const uint4* xq = xbase + (long)(g + 1) * 128;
            xn0 = __ldg(xq);
            xn1 = __ldg(xq + 32);
            xn2 = __ldg(xq + 64);
            xn3 = __ldg(xq + 96);
        }

        // compute step g
        unsigned a0h, a2h, a0l, a2l, a1h, a3h, a1l, a3l;
        cvt_hilo(w0c, a0h, a2h, a0l, a2l);     // row r:   a0=(k01) a2=(k23)
        cvt_hilo(w1c, a1h, a3h, a1l, a3l);     // row r+8
        {
            uint4 u = xc0;
            mma16816(acc[0], a0h, a1h, a2h, a3h, u.x, u.y);
            mma16816(acc[0], a0h, a1h, a2h, a3h, u.z, u.w);
            mma16816(acc[0], a0l, a1l, a2l, a3l, u.x, u.y);
            u = xc1;
            mma16816(acc[1], a0h, a1h, a2h, a3h, u.x, u.y);
            mma16816(acc[1], a0h, a1h, a2h, a3h, u.z, u.w);
            mma16816(acc[1], a0l, a1l, a2l, a3l, u.x, u.y);
            u = xc2;
            mma16816(acc[2], a0h, a1h, a2h, a3h, u.x, u.y);
            mma16816(acc[2], a0h, a1h, a2h, a3h, u.z, u.w);
            mma16816(acc[2], a0l, a1l, a2l, a3l, u.x, u.y);
            u = xc3;
            mma16816(acc[3], a0h, a1h, a2h, a3h, u.x, u.y);
            mma16816(acc[3], a0h, a1h, a2h, a3h, u.z, u.w);
            mma16816(acc[3], a0l, a1l, a2l, a3l, u.x, u.y);
        }

        // rotate
        w0c = w0n; w1c = w1n;
        xc0 = xn0; xc1 = xn1; xc2 = xn2; xc3 = xn3;
    }

    // epilogue: raw split-K partials (mapping validated R10/R11)
    int n0 = tile * 128 + wid * 16 + r;
    #pragma unroll
    for (int nf = 0; nf < 4; ++nf) {
        int b0 = nf * 8 + 2 * t;
        g_part[(long)(ky * 32 + b0)     * N + n0]     = acc[nf][0];
        g_part[(long)(ky * 32 + b0 + 1) * N + n0]     = acc[nf][1];
        g_part[(long)(ky * 32 + b0)     * N + n0 + 8] = acc[nf][2];
        g_part[(long)(ky * 32 + b0 + 1) * N + n0 + 8] = acc[nf][3];
    }
}

// ---------------- dense4 (4096 -> 64) ----------------
__global__ void dense4_kernel(const float* __restrict__ w4, const float* __restrict__ b4) {
    int n = blockIdx.x, tid = threadIdx.x;
    float acc[32];
    #pragma unroll
    for (int b = 0; b < 32; ++b) acc[b] = 0.f;
    const float* wr = w4 + n * 4096;
    for (int k = tid; k < 4096; k += 128) {
        float w = wr[k];
        #pragma unroll
        for (int b = 0; b < 32; ++b) acc[b] += g_act3[b * 4096 + k] * w;
    }
    __shared__ float red[4][32];
    int lane = tid & 31, wrp = tid >> 5;
    #pragma unroll
    for (int b = 0; b < 32; ++b) {
        float v = acc[b];
        v += __shfl_down_sync(0xffffffffu, v, 16);
        v += __shfl_down_sync(0xffffffffu, v, 8);
        v += __shfl_down_sync(0xffffffffu, v, 4);
        v += __shfl_down_sync(0xffffffffu, v, 2);
        v += __shfl_down_sync(0xffffffffu, v, 1);
        if (lane == 0) red[wrp][b] = v;
    }
    __syncthreads();
    if (tid < 32) {
        float s = red[0][tid] + red[1][tid] + red[2][tid] + red[3][tid] + b4[n];
        g_act4[tid * 64 + n] = fmaxf(s, 0.f);
    }
}

// ---------------- fused output (64 -> 16 -> 1) ----------------
__global__ void final_kernel(const float* __restrict__ wo, const float* __restrict__ bo,
                             const float* __restrict__ wf, const float* __restrict__ bf,
                             float* __restrict__ out) {
    int b = threadIdx.x;
    float res = bf[0];
    for (int j = 0; j < 16; ++j) {
        float o = bo[j];
        #pragma unroll
        for (int n = 0; n < 64; ++n) o += g_act4[b * 64 + n] * wo[j * 64 + n];
        res += o * wf[j];
    }
    out[b] = res;
}

extern "C" void kernel_launch(void* const* d_in, const int* in_sizes, int n_in,
                              void* d_out, int out_size) {
    const float* in  = (const float*)d_in[0];
    const float* cw  = (const float*)d_in[4];
    const float* cb  = (const float*)d_in[5];
    const float* w1  = (const float*)d_in[6];
    const float* b1  = (const float*)d_in[7];
    const float* w2  = (const float*)d_in[8];
    const float* b2  = (const float*)d_in[9];
    const float* w3  = (const float*)d_in[10];
    const float* b3  = (const float*)d_in[11];
    const float* w4  = (const float*)d_in[12];
    const float* b4  = (const float*)d_in[13];
    const float* wo  = (const float*)d_in[14];
    const float* bo  = (const float*)d_in[15];
    const float* wf  = (const float*)d_in[16];
    const float* bf  = (const float*)d_in[17];
    float* out = (float*)d_out;

    float *act0;
    uint4 *xpk0, *xpk1, *xpk2;
    cudaGetSymbolAddress((void**)&act0, g_act0);
    cudaGetSymbolAddress((void**)&xpk0, g_xpk0);
    cudaGetSymbolAddress((void**)&xpk1, g_xpk1);
    cudaGetSymbolAddress((void**)&xpk2, g_xpk2);

    conv_kernel<<<128, 128>>>(in, cw, cb);
    pack_kernel<<<672, 256>>>(act0, 21504, xpk0);
    marker_kernel<<<1, 32>>>();   // aligns dense1 gemm to ncu capture slot

    // dense1: 16384x21504 -> 128 tiles x split 2 = 256 CTAs, 672 k16-steps
    gemm_mma<<<dim3(128, 2), 256>>>(w1, xpk0, 16384, 21504, 672);
    reduce_pack<<<512, 256>>>(b1, 16384, 2, xpk1);

    // dense2: 4096x16384 -> 32 tiles x split 8 = 256 CTAs, 128 steps
    gemm_mma<<<dim3(32, 8), 256>>>(w2, xpk1, 4096, 16384, 128);
    reduce_pack<<<128, 256>>>(b2, 4096, 8, xpk2);

    // dense3: 4096x4096 -> 32 tiles x split 8 = 256 CTAs, 32 steps (fp32 out for dense4)
    gemm_mma<<<dim3(32, 8), 256>>>(w3, xpk2, 4096, 4096, 32);
    reduce_kernel<<<512, 256>>>(b3, 4096, 8);

    dense4_kernel<<<64, 128>>>(w4, b4);
    final_kernel<<<1, 32>>>(wo, bo, wf, bf, out);
}

// round 17
// speedup vs baseline: 1.5907x; 1.2856x over previous
#include <cuda_runtime.h>
#include <cstdint>

// ---------------- device scratch ----------------
__device__ __align__(16) float g_act0[32 * 21504];
__device__ __align__(16) float g_act3[32 * 4096];
__device__ __align__(16) float g_act4[32 * 64];
__device__ __align__(16) float g_part[1048576];        // max(2*32*16384, 8*32*4096)
__device__ __align__(16) uint4 g_xpk0[172032];         // 21504/16 * 128
__device__ __align__(16) uint4 g_xpk1[131072];         // 16384/16 * 128
__device__ __align__(16) uint4 g_xpk2[32768];          // 4096/16 * 128

// ---------------- PTX helpers ----------------
__device__ __forceinline__ void mma16816(float* d, unsigned a0, unsigned a1, unsigned a2, unsigned a3,
                                         unsigned b0, unsigned b1) {
    asm volatile("mma.sync.aligned.m16n8k16.row.col.f32.bf16.bf16.f32 "
                 "{%0,%1,%2,%3}, {%4,%5,%6,%7}, {%8,%9}, {%0,%1,%2,%3};"
                 : "+f"(d[0]), "+f"(d[1]), "+f"(d[2]), "+f"(d[3])
                 : "r"(a0), "r"(a1), "r"(a2), "r"(a3), "r"(b0), "r"(b1));
}
// float4 -> {hi01, hi23, lo01, lo23} packed bf16x2
__device__ __forceinline__ void cvt_hilo(float4 v, unsigned &h01, unsigned &h23,
                                         unsigned &l01, unsigned &l23) {
    asm("cvt.rn.bf16x2.f32 %0, %1, %2;" : "=r"(h01) : "f"(v.y), "f"(v.x));
    asm("cvt.rn.bf16x2.f32 %0, %1, %2;" : "=r"(h23) : "f"(v.w), "f"(v.z));
    float r0 = v.x - __uint_as_float(h01 << 16);
    float r1 = v.y - __uint_as_float(h01 & 0xffff0000u);
    float r2 = v.z - __uint_as_float(h23 << 16);
    float r3 = v.w - __uint_as_float(h23 & 0xffff0000u);
    asm("cvt.rn.bf16x2.f32 %0, %1, %2;" : "=r"(l01) : "f"(r1), "f"(r0));
    asm("cvt.rn.bf16x2.f32 %0, %1, %2;" : "=r"(l23) : "f"(r3), "f"(r2));
}

// ---------------- conv + permuted scatter ----------------
__global__ void conv_kernel(const float* __restrict__ in,
                            const float* __restrict__ cw,
                            const float* __restrict__ cb) {
    int b = blockIdx.x >> 2, f = blockIdx.x & 3, tid = threadIdx.x;
    __shared__ float xin[343], wsh[128], bsh[16];
    for (int i = tid; i < 343; i += 128) xin[i] = in[(b * 343 + i) * 5 + f];
    if (tid < 128) wsh[tid] = cw[tid];
    if (tid < 16)  bsh[tid] = cb[tid];
    __syncthreads();
    int h = b >> 4, base = (b & 15) * 1344 + f * 336;
    for (int l = tid; l < 336; l += 128) {
        #pragma unroll
        for (int c = 0; c < 16; ++c) {
            float s = bsh[c];
            #pragma unroll
            for (int k = 0; k < 8; ++k) s += xin[l + k] * wsh[c * 8 + k];
            g_act0[(2 * c + h) * 21504 + base + l] = fmaxf(s, 0.f);
        }
    }
}

// ---------------- pack fp32 X[32][K] -> fragment-ordered bf16 hi/lo uint4 ----------------
__global__ void pack_kernel(const float* __restrict__ src, int K, uint4* __restrict__ dst) {
    int i = blockIdx.x * 256 + threadIdx.x;
    if (i >= (K >> 4) * 128) return;
    int kb = i >> 7, ng = (i >> 5) & 3, lane = i & 31;
    int b = ng * 8 + (lane >> 2), c = kb * 16 + (lane & 3) * 4;
    float4 v = *(const float4*)(src + (long)b * K + c);
    uint4 o;
    cvt_hilo(v, o.x, o.y, o.z, o.w);
    dst[i] = o;
}

// dummy so dense1 gemm lands at ncu's capture index
__global__ void marker_kernel() {}

// ---------------- split-K reduce + bias + relu -> packed X ----------------
__global__ void reduce_pack(const float* __restrict__ bias, int N, int ks, uint4* __restrict__ dst) {
    int i = blockIdx.x * 256 + threadIdx.x;
    if (i >= (N >> 4) * 128) return;
    int kb = i >> 7, ng = (i >> 5) & 3, lane = i & 31;
    int b = ng * 8 + (lane >> 2), c = kb * 16 + (lane & 3) * 4;
    float4 s = *(const float4*)(bias + c);
    for (int si = 0; si < ks; ++si) {
        float4 p = *(const float4*)(g_part + ((long)(si * 32 + b)) * N + c);
        s.x += p.x; s.y += p.y; s.z += p.z; s.w += p.w;
    }
    s.x = fmaxf(s.x, 0.f); s.y = fmaxf(s.y, 0.f);
    s.z = fmaxf(s.z, 0.f); s.w = fmaxf(s.w, 0.f);
    uint4 o;
    cvt_hilo(s, o.x, o.y, o.z, o.w);
    dst[i] = o;
}

// ---------------- split-K reduce + bias + relu -> fp32 (dense4 input) ----------------
__global__ void reduce_kernel(const float* __restrict__ bias, int N, int ks) {
    int idx = blockIdx.x * 256 + threadIdx.x;
    if (idx >= 32 * N) return;
    float s = bias[idx % N];
    for (int si = 0; si < ks; ++si) s += g_part[(long)si * 32 * N + idx];
    g_act3[idx] = fmaxf(s, 0.f);
}

// ---------------- bf16x3 mma.sync GEMM: LDG-direct, depth-4 W / depth-2 X pipeline ----------------
// D[n,b] = sum_k W[n,k]*X[b,k]; tile M=128 x N=32; step = k16; split-K raw partials.
// nsteps must be a multiple of 4.
__global__ __launch_bounds__(256, 2)
void gemm_mma(const float* __restrict__ W, const uint4* __restrict__ xpk,
              int N, int K, int nsteps) {
    int tid = threadIdx.x, wid = tid >> 5, lane = tid & 31;
    int tile = blockIdx.x, ky = blockIdx.y;
    int r = lane >> 2, t = lane & 3;
    long k0 = (long)ky * nsteps * 16;

    const float* wp0 = W + (long)(tile * 128 + wid * 16 + r) * K + k0 + t * 4;
    const float* wp1 = wp0 + 8L * K;
    const uint4* xbase = xpk + (long)(ky * nsteps) * 128 + lane;

    float acc[4][4];
    #pragma unroll
    for (int i = 0; i < 4; ++i)
        #pragma unroll
        for (int j = 0; j < 4; ++j) acc[i][j] = 0.f;

    // pipeline buffers: W depth 4, X depth 2
    float4 wa[4], wb[4];
    uint4 xv[2][4];
    #pragma unroll
    for (int i = 0; i < 4; ++i) {
        wa[i] = __ldg((const float4*)(wp0 + i * 16));
        wb[i] = __ldg((const float4*)(wp1 + i * 16));
    }
    #pragma unroll
    for (int i = 0; i < 2; ++i) {
        const uint4* xq = xbase + (long)i * 128;
        xv[i][0] = __ldg(xq);
        xv[i][1] = __ldg(xq + 32);
        xv[i][2] = __ldg(xq + 64);
        xv[i][3] = __ldg(xq + 96);
    }

    for (int gb = 0; gb < nsteps; gb += 4) {
        #pragma unroll
        for (int ph = 0; ph < 4; ++ph) {
            int g = gb + ph;
            int xp = ph & 1;

            // compute step g from wa/wb[ph], xv[xp]
            unsigned a0h, a2h, a0l, a2l, a1h, a3h, a1l, a3l;
            cvt_hilo(wa[ph], a0h, a2h, a0l, a2l);   // row r:   a0=(k01) a2=(k23)
            cvt_hilo(wb[ph], a1h, a3h, a1l, a3l);   // row r+8
            #pragma unroll
            for (int ng = 0; ng < 4; ++ng) {
                uint4 u = xv[xp][ng];
                mma16816(acc[ng], a0h, a1h, a2h, a3h, u.x, u.y);
                mma16816(acc[ng], a0h, a1h, a2h, a3h, u.z, u.w);
                mma16816(acc[ng], a0l, a1l, a2l, a3l, u.x, u.y);
            }

            // prefetch: W step g+4 into slot ph (consumed 3 phases later)
            if (g + 4 < nsteps) {
                long o = (long)(g + 4) * 16;
                wa[ph] = __ldg((const float4*)(wp0 + o));
                wb[ph] = __ldg((const float4*)(wp1 + o));
            }
            // prefetch: X step g+2 into slot xp (consumed next same-parity phase)
            if (g + 2 < nsteps) {
                const uint4* xq = xbase + (long)(g + 2) * 128;
                xv[xp][0] = __ldg(xq);
                xv[xp][1] = __ldg(xq + 32);
                xv[xp][2] = __ldg(xq + 64);
                xv[xp][3] = __ldg(xq + 96);
            }
        }
    }

    // epilogue: raw split-K partials (mapping validated R10/R11)
    int n0 = tile * 128 + wid * 16 + r;
    #pragma unroll
    for (int nf = 0; nf < 4; ++nf) {
        int b0 = nf * 8 + 2 * t;
        g_part[(long)(ky * 32 + b0)     * N + n0]     = acc[nf][0];
        g_part[(long)(ky * 32 + b0 + 1) * N + n0]     = acc[nf][1];
        g_part[(long)(ky * 32 + b0)     * N + n0 + 8] = acc[nf][2];
        g_part[(long)(ky * 32 + b0 + 1) * N + n0 + 8] = acc[nf][3];
    }
}

// ---------------- dense4 (4096 -> 64) ----------------
__global__ void dense4_kernel(const float* __restrict__ w4, const float* __restrict__ b4) {
    int n = blockIdx.x, tid = threadIdx.x;
    float acc[32];
    #pragma unroll
    for (int b = 0; b < 32; ++b) acc[b] = 0.f;
    const float* wr = w4 + n * 4096;
    for (int k = tid; k < 4096; k += 128) {
        float w = wr[k];
        #pragma unroll
        for (int b = 0; b < 32; ++b) acc[b] += g_act3[b * 4096 + k] * w;
    }
    __shared__ float red[4][32];
    int lane = tid & 31, wrp = tid >> 5;
    #pragma unroll
    for (int b = 0; b < 32; ++b) {
        float v = acc[b];
        v += __shfl_down_sync(0xffffffffu, v, 16);
        v += __shfl_down_sync(0xffffffffu, v, 8);
        v += __shfl_down_sync(0xffffffffu, v, 4);
        v += __shfl_down_sync(0xffffffffu, v, 2);
        v += __shfl_down_sync(0xffffffffu, v, 1);
        if (lane == 0) red[wrp][b] = v;
    }
    __syncthreads();
    if (tid < 32) {
        float s = red[0][tid] + red[1][tid] + red[2][tid] + red[3][tid] + b4[n];
        g_act4[tid * 64 + n] = fmaxf(s, 0.f);
    }
}

// ---------------- fused output (64 -> 16 -> 1) ----------------
__global__ void final_kernel(const float* __restrict__ wo, const float* __restrict__ bo,
                             const float* __restrict__ wf, const float* __restrict__ bf,
                             float* __restrict__ out) {
    int b = threadIdx.x;
    float res = bf[0];
    for (int j = 0; j < 16; ++j) {
        float o = bo[j];
        #pragma unroll
        for (int n = 0; n < 64; ++n) o += g_act4[b * 64 + n] * wo[j * 64 + n];
        res += o * wf[j];
    }
    out[b] = res;
}

extern "C" void kernel_launch(void* const* d_in, const int* in_sizes, int n_in,
                              void* d_out, int out_size) {
    const float* in  = (const float*)d_in[0];
    const float* cw  = (const float*)d_in[4];
    const float* cb  = (const float*)d_in[5];
    const float* w1  = (const float*)d_in[6];
    const float* b1  = (const float*)d_in[7];
    const float* w2  = (const float*)d_in[8];
    const float* b2  = (const float*)d_in[9];
    const float* w3  = (const float*)d_in[10];
    const float* b3  = (const float*)d_in[11];
    const float* w4  = (const float*)d_in[12];
    const float* b4  = (const float*)d_in[13];
    const float* wo  = (const float*)d_in[14];
    const float* bo  = (const float*)d_in[15];
    const float* wf  = (const float*)d_in[16];
    const float* bf  = (const float*)d_in[17];
    float* out = (float*)d_out;

    float *act0;
    uint4 *xpk0, *xpk1, *xpk2;
    cudaGetSymbolAddress((void**)&act0, g_act0);
    cudaGetSymbolAddress((void**)&xpk0, g_xpk0);
    cudaGetSymbolAddress((void**)&xpk1, g_xpk1);
    cudaGetSymbolAddress((void**)&xpk2, g_xpk2);

    conv_kernel<<<128, 128>>>(in, cw, cb);
    pack_kernel<<<672, 256>>>(act0, 21504, xpk0);
    marker_kernel<<<1, 32>>>();   // aligns dense1 gemm to ncu capture slot

    // dense1: 16384x21504 -> 128 tiles x split 2 = 256 CTAs, 672 k16-steps
    gemm_mma<<<dim3(128, 2), 256>>>(w1, xpk0, 16384, 21504, 672);
    reduce_pack<<<512, 256>>>(b1, 16384, 2, xpk1);

    // dense2: 4096x16384 -> 32 tiles x split 8 = 256 CTAs, 128 steps
    gemm_mma<<<dim3(32, 8), 256>>>(w2, xpk1, 4096, 16384, 128);
    reduce_pack<<<128, 256>>>(b2, 4096, 8, xpk2);

    // dense3: 4096x4096 -> 32 tiles x split 8 = 256 CTAs, 32 steps (fp32 out for dense4)
    gemm_mma<<<dim3(32, 8), 256>>>(w3, xpk2, 4096, 4096, 32);
    reduce_kernel<<<512, 256>>>(b3, 4096, 8);

    dense4_kernel<<<64, 128>>>(w4, b4);
    final_kernel<<<1, 32>>>(wo, bo, wf, bf, out);
}